// round 10
// baseline (speedup 1.0000x reference)
#include <cuda_runtime.h>
#include <cuda_fp16.h>
#include <cstdint>

#define NT 256
#define BM 256                 // CTA rows
#define BK 32                  // K floats per tile -> 16 half2 words
#define KP 16                  // k-pair words per tile
#define AS_STRIDE 20           // u32 stride [m][kp]
#define WS_STRIDE 136          // u32 stride [kp][n]
#define A_TILE (BM * AS_STRIDE)        // 5120 u32
#define W_TILE (KP * WS_STRIDE)        // 2176 u32
#define OFF_W  (2 * A_TILE)
#define OFF_BIAS (2 * A_TILE + 2 * W_TILE)
#define SMEM_BYTES ((2 * A_TILE + 2 * W_TILE + 128) * 4)   // 58880 B

// Pre-scaled fp16x2-packed weights, [job][kp][n=128] u32:
// job 0/1: region0 cb=0/1 (kp=192) ; job 2-4: region 1..3 (kp=256)
__device__ uint32_t g_wt[147456];

__device__ __forceinline__ uint32_t smem_u32(const void* p) {
    uint32_t a;
    asm("{ .reg .u64 t; cvta.to.shared.u64 t, %1; cvt.u32.u64 %0, t; }" : "=r"(a) : "l"(p));
    return a;
}
__device__ __forceinline__ void cp16(uint32_t dst, const void* src) {
    asm volatile("cp.async.ca.shared.global [%0], [%1], 16;" :: "r"(dst), "l"(src));
}
__device__ __forceinline__ uint32_t pack_h2(float lo, float hi) {
    half2 h = __floats2half2_rn(lo, hi);
    return *(uint32_t*)&h;
}
__device__ __forceinline__ void mma_f16(float* d, const uint32_t* a, const uint32_t* b) {
    asm volatile(
        "mma.sync.aligned.m16n8k16.row.col.f32.f16.f16.f32 "
        "{%0,%1,%2,%3}, {%4,%5,%6,%7}, {%8,%9}, {%0,%1,%2,%3};"
        : "+f"(d[0]), "+f"(d[1]), "+f"(d[2]), "+f"(d[3])
        : "r"(a[0]), "r"(a[1]), "r"(a[2]), "r"(a[3]), "r"(b[0]), "r"(b[1]));
}

// ---------------- weight prep: fold scales + fp16 pack (k-pairs) ----------------
__global__ void prep_wt(const float* __restrict__ w000, const float* __restrict__ w110,
                        const float* __restrict__ w011, const float* __restrict__ w101,
                        const float* __restrict__ w111)
{
    const float SQK0 = 0.05103103630798288f;
    const float SQK1 = 0.04419417382415922f;
    const float IS3  = 0.57735026918962584f;
    const float IS2  = 0.70710678118654752f;

    int idx = blockIdx.x * 256 + threadIdx.x;
    if (idx >= 147456) return;
    int job, rem;
    if (idx < 49152) { job = idx / 24576; rem = idx % 24576; }
    else             { int t = idx - 49152; job = 2 + t / 32768; rem = t % 32768; }
    int kp = rem >> 7, n = rem & 127;

    float w2[2];
    #pragma unroll
    for (int h = 0; h < 2; h++) {
        int k = 2 * kp + h;
        float v;
        if (job < 2) {
            int cb = job;
            if (k < 256) v = SQK0 * w000[k * 256 + cb * 128 + n];
            else         v = SQK0 * IS3 * w110[(k - 256) * 256 + cb * 128 + n];
        } else {
            if (k < 256)      v = SQK1 * w011[k * 128 + n];
            else if (k < 384) v = SQK1 * w101[(k - 256) * 128 + n];
            else              v = SQK1 * IS2 * w111[(k - 384) * 128 + n];
        }
        w2[h] = v;
    }
    g_wt[idx] = pack_h2(w2[0], w2[1]);
}

// ---------------- main kernel ----------------
__global__ void __launch_bounds__(NT, 1)
tpr_kernel(const float* __restrict__ x, const float* __restrict__ y,
           const float* __restrict__ b0, float* __restrict__ out, int B)
{
    extern __shared__ uint32_t sm[];
    const uint32_t sb = smem_u32(sm);

    const int job  = blockIdx.x;
    const int row0 = blockIdx.y * BM;
    const int tid  = threadIdx.x;
    const int wid  = tid >> 5;
    const int lane = tid & 31;
    const int qr   = lane >> 2;
    const int qc   = lane & 3;
    const int wm   = wid & 3;     // warp m (64 rows)
    const int wn   = wid >> 2;    // warp n (64 cols)

    int region, cb;
    if (job < 2) { region = 0; cb = job; } else { region = job - 1; cb = 0; }
    const int i0 = region - 1;
    const int j1 = (i0 + 1) % 3;
    const int j2 = (i0 + 2) % 3;
    const int KT = (region == 0) ? 12 : 16;
    const uint32_t* wbase = g_wt + ((job < 2) ? job * 24576 : 49152 + (job - 2) * 32768);

    // staging role: one row per thread, full BK=32 k per tile (two 16-k halves)
    const int frow = row0 + tid;
    const bool valid = frow < B;
    const float* xr = x + (size_t)frow * 640;
    float yv[4] = {0.f, 0.f, 0.f, 0.f};
    if (valid) {
        float4 t = *(const float4*)(y + (size_t)frow * 4);
        yv[0] = t.x; yv[1] = t.y; yv[2] = t.z; yv[3] = t.w;
    }
    if (region == 0 && tid < 128)
        ((float*)(sm + OFF_BIAS))[tid] = b0[cb * 128 + tid];

    float acc[4][8][4];
    #pragma unroll
    for (int mi = 0; mi < 4; mi++)
        #pragma unroll
        for (int ni = 0; ni < 8; ni++)
            #pragma unroll
            for (int c = 0; c < 4; c++) acc[mi][ni][c] = 0.f;

    // ---- W tile: cp.async straight copy (pre-packed fp16x2) ----
    auto issueW = [&](int kt, int b) {
        const uint32_t dbase = sb + (OFF_W + b * W_TILE) * 4;
        const uint32_t* src = wbase + (size_t)(kt * KP) * 128;
        #pragma unroll
        for (int i = 0; i < 2; i++) {
            int idx = tid + i * NT;        // over 512 16B chunks
            int kw = idx >> 5, c16 = idx & 31;
            cp16(dbase + (uint32_t)(kw * WS_STRIDE + c16 * 4) * 4,
                 src + kw * 128 + c16 * 4);
        }
        asm volatile("cp.async.commit_group;" ::: "memory");
    };

    // ---- A tile: compute 16 gated features (one k-half), pack to 8 u32 ----
    auto pack_half = [&](int kg0, uint32_t* u) {
        if (!valid) {
            #pragma unroll
            for (int c = 0; c < 8; c++) u[c] = 0u;
        } else if (kg0 < 256) {
            float s = (region == 0) ? yv[0] : yv[1 + i0];
            const float4* p = (const float4*)(xr + kg0);
            #pragma unroll
            for (int q = 0; q < 4; q++) {
                float4 a = p[q];
                u[2*q]   = pack_h2(a.x * s, a.y * s);
                u[2*q+1] = pack_h2(a.z * s, a.w * s);
            }
        } else {
            int u0, mode;
            if (region == 0)    { u0 = kg0 - 256; mode = 0; }
            else if (kg0 < 384) { u0 = kg0 - 256; mode = 1; }
            else                { u0 = kg0 - 384; mode = 2; }
            const float4* p = (const float4*)(xr + 256 + 3 * u0);
            // process 4 features (3 float4s) at a time -> 2 packed u32
            #pragma unroll
            for (int g = 0; g < 4; g++) {
                float v[12];
                *(float4*)&v[0] = p[3*g];
                *(float4*)&v[4] = p[3*g + 1];
                *(float4*)&v[8] = p[3*g + 2];
                float f[4];
                #pragma unroll
                for (int jj = 0; jj < 4; jj++) {
                    float e0 = v[3*jj], e1 = v[3*jj+1], e2 = v[3*jj+2];
                    if (mode == 0) {
                        f[jj] = e0 * yv[1] + e1 * yv[2] + e2 * yv[3];
                    } else if (mode == 1) {
                        float xi = (i0 == 0) ? e0 : ((i0 == 1) ? e1 : e2);
                        f[jj] = xi * yv[0];
                    } else {
                        float xa = (j1 == 0) ? e0 : ((j1 == 1) ? e1 : e2);
                        float xb = (j2 == 0) ? e0 : ((j2 == 1) ? e1 : e2);
                        f[jj] = xa * yv[1 + j2] - xb * yv[1 + j1];
                    }
                }
                u[2*g]   = pack_h2(f[0], f[1]);
                u[2*g+1] = pack_h2(f[2], f[3]);
            }
        }
    };
    auto stageA = [&](int kt, int b) {
        uint32_t* ap = sm + b * A_TILE + tid * AS_STRIDE;
        uint32_t u[8];
        pack_half(kt * BK, u);
        *(uint4*)(ap)     = make_uint4(u[0], u[1], u[2], u[3]);
        *(uint4*)(ap + 4) = make_uint4(u[4], u[5], u[6], u[7]);
        pack_half(kt * BK + 16, u);
        *(uint4*)(ap + 8)  = make_uint4(u[0], u[1], u[2], u[3]);
        *(uint4*)(ap + 12) = make_uint4(u[4], u[5], u[6], u[7]);
    };

    // ---------- prologue ----------
    issueW(0, 0);
    stageA(0, 0);

    // ---------- main loop: 1 barrier / tile ----------
    for (int kt = 0; kt < KT; kt++) {
        const int b = kt & 1;
        asm volatile("cp.async.wait_group 0;" ::: "memory");
        __syncthreads();

        const bool more = (kt + 1 < KT);
        if (more) { issueW(kt + 1, b ^ 1); stageA(kt + 1, b ^ 1); }

        const uint32_t* Ab = sm + b * A_TILE;
        const uint32_t* Wb = sm + OFF_W + b * W_TILE;
        #pragma unroll
        for (int ks = 0; ks < 2; ks++) {
            const int base = ks * 8;        // k-pair base (k16 per MMA)
            uint32_t a[4][4];
            #pragma unroll
            for (int mi = 0; mi < 4; mi++) {
                const uint32_t* p = &Ab[(wm * 64 + mi * 16 + qr) * AS_STRIDE + base + qc];
                a[mi][0] = p[0];
                a[mi][1] = p[8 * AS_STRIDE];
                a[mi][2] = p[4];
                a[mi][3] = p[8 * AS_STRIDE + 4];
            }
            #pragma unroll
            for (int ni = 0; ni < 8; ni++) {
                uint32_t bb[2];
                const uint32_t* q = &Wb[(base + qc) * WS_STRIDE + wn * 64 + ni * 8 + qr];
                bb[0] = q[0];
                bb[1] = q[4 * WS_STRIDE];
                #pragma unroll
                for (int mi = 0; mi < 4; mi++)
                    mma_f16(acc[mi][ni], a[mi], bb);
            }
        }
    }

    // ---------- epilogue ----------
    const float* bias = (const float*)(sm + OFF_BIAS);
    #pragma unroll
    for (int mi = 0; mi < 4; mi++) {
        #pragma unroll
        for (int half = 0; half < 2; half++) {
            int row = row0 + wm * 64 + mi * 16 + qr + half * 8;
            if (row >= B) continue;
            if (region == 0) {
                float* o = out + (size_t)row * 640 + cb * 128;
                #pragma unroll
                for (int ni = 0; ni < 8; ni++) {
                    int col = wn * 64 + ni * 8 + qc * 2;
                    float2 v = make_float2(acc[mi][ni][half * 2]     + bias[col],
                                           acc[mi][ni][half * 2 + 1] + bias[col + 1]);
                    *(float2*)(o + col) = v;
                }
            } else {
                float* o = out + (size_t)row * 640 + 256 + i0;
                #pragma unroll
                for (int ni = 0; ni < 8; ni++) {
                    int col = wn * 64 + ni * 8 + qc * 2;
                    o[col * 3]       = acc[mi][ni][half * 2];
                    o[(col + 1) * 3] = acc[mi][ni][half * 2 + 1];
                }
            }
        }
    }
}

extern "C" void kernel_launch(void* const* d_in, const int* in_sizes, int n_in,
                              void* d_out, int out_size)
{
    const float* x    = (const float*)d_in[0];
    const float* y    = (const float*)d_in[1];
    const float* w000 = (const float*)d_in[2];
    const float* w110 = (const float*)d_in[3];
    const float* w011 = (const float*)d_in[4];
    const float* w101 = (const float*)d_in[5];
    const float* w111 = (const float*)d_in[6];
    const float* b0   = (const float*)d_in[7];
    int B = in_sizes[0] / 640;

    cudaFuncSetAttribute(tpr_kernel, cudaFuncAttributeMaxDynamicSharedMemorySize,
                         SMEM_BYTES);

    prep_wt<<<(147456 + 255) / 256, 256>>>(w000, w110, w011, w101, w111);

    dim3 grid(5, (B + BM - 1) / BM);
    tpr_kernel<<<grid, NT, SMEM_BYTES>>>(x, y, b0, (float*)d_out, B);
}

// round 11
// speedup vs baseline: 1.0862x; 1.0862x over previous
#include <cuda_runtime.h>
#include <cuda_fp16.h>
#include <cstdint>

#define NT 128                 // 4 warps: 2 (m) x 2 (n), warp tile 64x64
#define BM 128                 // CTA rows
#define BK 32                  // K floats per tile -> 16 half2 words
#define KP 16                  // k-pair words per tile
#define AS_STRIDE 20           // u32 stride [m][kp]
#define WS_STRIDE 136          // u32 stride [kp][n]
#define A_TILE (BM * AS_STRIDE)        // 2560 u32
#define W_TILE (KP * WS_STRIDE)        // 2176 u32
#define OFF_W  (2 * A_TILE)
#define OFF_BIAS (2 * A_TILE + 2 * W_TILE)
#define SMEM_BYTES ((2 * A_TILE + 2 * W_TILE + 128) * 4)   // 38400 B

// Pre-scaled fp16x2-packed weights, [job][kp][n=128] u32:
// job 0/1: region0 cb=0/1 (kp=192) ; job 2-4: region 1..3 (kp=256)
__device__ uint32_t g_wt[147456];

__device__ __forceinline__ uint32_t smem_u32(const void* p) {
    uint32_t a;
    asm("{ .reg .u64 t; cvta.to.shared.u64 t, %1; cvt.u32.u64 %0, t; }" : "=r"(a) : "l"(p));
    return a;
}
__device__ __forceinline__ void cp16(uint32_t dst, const void* src) {
    asm volatile("cp.async.ca.shared.global [%0], [%1], 16;" :: "r"(dst), "l"(src));
}
__device__ __forceinline__ uint32_t pack_h2(float lo, float hi) {
    half2 h = __floats2half2_rn(lo, hi);
    return *(uint32_t*)&h;
}
__device__ __forceinline__ void mma_f16(float* d, const uint32_t* a, const uint32_t* b) {
    asm volatile(
        "mma.sync.aligned.m16n8k16.row.col.f32.f16.f16.f32 "
        "{%0,%1,%2,%3}, {%4,%5,%6,%7}, {%8,%9}, {%0,%1,%2,%3};"
        : "+f"(d[0]), "+f"(d[1]), "+f"(d[2]), "+f"(d[3])
        : "r"(a[0]), "r"(a[1]), "r"(a[2]), "r"(a[3]), "r"(b[0]), "r"(b[1]));
}

// ---------------- weight prep: fold scales + fp16 pack (k-pairs) ----------------
__global__ void prep_wt(const float* __restrict__ w000, const float* __restrict__ w110,
                        const float* __restrict__ w011, const float* __restrict__ w101,
                        const float* __restrict__ w111)
{
    const float SQK0 = 0.05103103630798288f;
    const float SQK1 = 0.04419417382415922f;
    const float IS3  = 0.57735026918962584f;
    const float IS2  = 0.70710678118654752f;

    int idx = blockIdx.x * 256 + threadIdx.x;
    if (idx >= 147456) return;
    int job, rem;
    if (idx < 49152) { job = idx / 24576; rem = idx % 24576; }
    else             { int t = idx - 49152; job = 2 + t / 32768; rem = t % 32768; }
    int kp = rem >> 7, n = rem & 127;

    float w2[2];
    #pragma unroll
    for (int h = 0; h < 2; h++) {
        int k = 2 * kp + h;
        float v;
        if (job < 2) {
            int cb = job;
            if (k < 256) v = SQK0 * w000[k * 256 + cb * 128 + n];
            else         v = SQK0 * IS3 * w110[(k - 256) * 256 + cb * 128 + n];
        } else {
            if (k < 256)      v = SQK1 * w011[k * 128 + n];
            else if (k < 384) v = SQK1 * w101[(k - 256) * 128 + n];
            else              v = SQK1 * IS2 * w111[(k - 384) * 128 + n];
        }
        w2[h] = v;
    }
    g_wt[idx] = pack_h2(w2[0], w2[1]);
}

// ---------------- main kernel ----------------
__global__ void __launch_bounds__(NT, 2)
tpr_kernel(const float* __restrict__ x, const float* __restrict__ y,
           const float* __restrict__ b0, float* __restrict__ out, int B)
{
    extern __shared__ uint32_t sm[];
    const uint32_t sb = smem_u32(sm);

    const int job  = blockIdx.x;
    const int row0 = blockIdx.y * BM;
    const int tid  = threadIdx.x;
    const int wid  = tid >> 5;
    const int lane = tid & 31;
    const int qr   = lane >> 2;
    const int qc   = lane & 3;
    const int wm   = wid & 1;     // warp m (64 rows)
    const int wn   = wid >> 1;    // warp n (64 cols)

    int region, cb;
    if (job < 2) { region = 0; cb = job; } else { region = job - 1; cb = 0; }
    const int i0 = region - 1;
    const int j1 = (i0 + 1) % 3;
    const int j2 = (i0 + 2) % 3;
    const int KT = (region == 0) ? 12 : 16;
    const uint32_t* wbase = g_wt + ((job < 2) ? job * 24576 : 49152 + (job - 2) * 32768);

    // staging role: one row per thread, full BK=32 k per tile (two 16-k halves)
    const int frow = row0 + tid;
    const bool valid = frow < B;
    const float* xr = x + (size_t)frow * 640;
    float yv[4] = {0.f, 0.f, 0.f, 0.f};
    if (valid) {
        float4 t = *(const float4*)(y + (size_t)frow * 4);
        yv[0] = t.x; yv[1] = t.y; yv[2] = t.z; yv[3] = t.w;
    }
    if (region == 0)
        ((float*)(sm + OFF_BIAS))[tid] = b0[cb * 128 + tid];

    float acc[4][8][4];
    #pragma unroll
    for (int mi = 0; mi < 4; mi++)
        #pragma unroll
        for (int ni = 0; ni < 8; ni++)
            #pragma unroll
            for (int c = 0; c < 4; c++) acc[mi][ni][c] = 0.f;

    // ---- W tile: cp.async straight copy (pre-packed fp16x2) ----
    auto issueW = [&](int kt, int b) {
        const uint32_t dbase = sb + (OFF_W + b * W_TILE) * 4;
        const uint32_t* src = wbase + (size_t)(kt * KP) * 128;
        #pragma unroll
        for (int i = 0; i < 4; i++) {
            int idx = tid + i * NT;        // over 512 16B chunks
            int kw = idx >> 5, c16 = idx & 31;
            cp16(dbase + (uint32_t)(kw * WS_STRIDE + c16 * 4) * 4,
                 src + kw * 128 + c16 * 4);
        }
        asm volatile("cp.async.commit_group;" ::: "memory");
    };

    // ---- A tile: compute 16 gated features (one k-half), pack to 8 u32 ----
    auto pack_half = [&](int kg0, uint32_t* u) {
        if (!valid) {
            #pragma unroll
            for (int c = 0; c < 8; c++) u[c] = 0u;
        } else if (kg0 < 256) {
            float s = (region == 0) ? yv[0] : yv[1 + i0];
            const float4* p = (const float4*)(xr + kg0);
            #pragma unroll
            for (int q = 0; q < 4; q++) {
                float4 a = p[q];
                u[2*q]   = pack_h2(a.x * s, a.y * s);
                u[2*q+1] = pack_h2(a.z * s, a.w * s);
            }
        } else {
            int u0, mode;
            if (region == 0)    { u0 = kg0 - 256; mode = 0; }
            else if (kg0 < 384) { u0 = kg0 - 256; mode = 1; }
            else                { u0 = kg0 - 384; mode = 2; }
            const float4* p = (const float4*)(xr + 256 + 3 * u0);
            #pragma unroll
            for (int g = 0; g < 4; g++) {
                float v[12];
                *(float4*)&v[0] = p[3*g];
                *(float4*)&v[4] = p[3*g + 1];
                *(float4*)&v[8] = p[3*g + 2];
                float f[4];
                #pragma unroll
                for (int jj = 0; jj < 4; jj++) {
                    float e0 = v[3*jj], e1 = v[3*jj+1], e2 = v[3*jj+2];
                    if (mode == 0) {
                        f[jj] = e0 * yv[1] + e1 * yv[2] + e2 * yv[3];
                    } else if (mode == 1) {
                        float xi = (i0 == 0) ? e0 : ((i0 == 1) ? e1 : e2);
                        f[jj] = xi * yv[0];
                    } else {
                        float xa = (j1 == 0) ? e0 : ((j1 == 1) ? e1 : e2);
                        float xb = (j2 == 0) ? e0 : ((j2 == 1) ? e1 : e2);
                        f[jj] = xa * yv[1 + j2] - xb * yv[1 + j1];
                    }
                }
                u[2*g]   = pack_h2(f[0], f[1]);
                u[2*g+1] = pack_h2(f[2], f[3]);
            }
        }
    };
    auto stageA = [&](int kt, int b) {
        uint32_t* ap = sm + b * A_TILE + tid * AS_STRIDE;
        uint32_t u[8];
        pack_half(kt * BK, u);
        *(uint4*)(ap)     = make_uint4(u[0], u[1], u[2], u[3]);
        *(uint4*)(ap + 4) = make_uint4(u[4], u[5], u[6], u[7]);
        pack_half(kt * BK + 16, u);
        *(uint4*)(ap + 8)  = make_uint4(u[0], u[1], u[2], u[3]);
        *(uint4*)(ap + 12) = make_uint4(u[4], u[5], u[6], u[7]);
    };

    // ---------- prologue ----------
    issueW(0, 0);
    stageA(0, 0);

    // ---------- main loop: 1 barrier / tile ----------
    for (int kt = 0; kt < KT; kt++) {
        const int b = kt & 1;
        asm volatile("cp.async.wait_group 0;" ::: "memory");
        __syncthreads();

        const bool more = (kt + 1 < KT);
        if (more) { issueW(kt + 1, b ^ 1); stageA(kt + 1, b ^ 1); }

        const uint32_t* Ab = sm + b * A_TILE;
        const uint32_t* Wb = sm + OFF_W + b * W_TILE;
        #pragma unroll
        for (int ks = 0; ks < 2; ks++) {
            const int base = ks * 8;        // k-pair base (k16 per MMA)
            uint32_t a[4][4];
            #pragma unroll
            for (int mi = 0; mi < 4; mi++) {
                const uint32_t* p = &Ab[(wm * 64 + mi * 16 + qr) * AS_STRIDE + base + qc];
                a[mi][0] = p[0];
                a[mi][1] = p[8 * AS_STRIDE];
                a[mi][2] = p[4];
                a[mi][3] = p[8 * AS_STRIDE + 4];
            }
            #pragma unroll
            for (int ni = 0; ni < 8; ni++) {
                uint32_t bb[2];
                const uint32_t* q = &Wb[(base + qc) * WS_STRIDE + wn * 64 + ni * 8 + qr];
                bb[0] = q[0];
                bb[1] = q[4 * WS_STRIDE];
                #pragma unroll
                for (int mi = 0; mi < 4; mi++)
                    mma_f16(acc[mi][ni], a[mi], bb);
            }
        }
    }

    // ---------- epilogue ----------
    const float* bias = (const float*)(sm + OFF_BIAS);
    #pragma unroll
    for (int mi = 0; mi < 4; mi++) {
        #pragma unroll
        for (int half = 0; half < 2; half++) {
            int row = row0 + wm * 64 + mi * 16 + qr + half * 8;
            if (row >= B) continue;
            if (region == 0) {
                float* o = out + (size_t)row * 640 + cb * 128;
                #pragma unroll
                for (int ni = 0; ni < 8; ni++) {
                    int col = wn * 64 + ni * 8 + qc * 2;
                    float2 v = make_float2(acc[mi][ni][half * 2]     + bias[col],
                                           acc[mi][ni][half * 2 + 1] + bias[col + 1]);
                    *(float2*)(o + col) = v;
                }
            } else {
                float* o = out + (size_t)row * 640 + 256 + i0;
                #pragma unroll
                for (int ni = 0; ni < 8; ni++) {
                    int col = wn * 64 + ni * 8 + qc * 2;
                    o[col * 3]       = acc[mi][ni][half * 2];
                    o[(col + 1) * 3] = acc[mi][ni][half * 2 + 1];
                }
            }
        }
    }
}

extern "C" void kernel_launch(void* const* d_in, const int* in_sizes, int n_in,
                              void* d_out, int out_size)
{
    const float* x    = (const float*)d_in[0];
    const float* y    = (const float*)d_in[1];
    const float* w000 = (const float*)d_in[2];
    const float* w110 = (const float*)d_in[3];
    const float* w011 = (const float*)d_in[4];
    const float* w101 = (const float*)d_in[5];
    const float* w111 = (const float*)d_in[6];
    const float* b0   = (const float*)d_in[7];
    int B = in_sizes[0] / 640;

    cudaFuncSetAttribute(tpr_kernel, cudaFuncAttributeMaxDynamicSharedMemorySize,
                         SMEM_BYTES);

    prep_wt<<<(147456 + 255) / 256, 256>>>(w000, w110, w011, w101, w111);

    dim3 grid(5, (B + BM - 1) / BM);
    tpr_kernel<<<grid, NT, SMEM_BYTES>>>(x, y, b0, (float*)d_out, B);
}

// round 12
// speedup vs baseline: 1.5747x; 1.4497x over previous
#include <cuda_runtime.h>
#include <cuda_fp16.h>
#include <cstdint>

#define NT 256                 // 8 warps: 4 (m) x 2 (n), warp tile 32x64
#define BM 128
#define BK 32                  // K floats per tile -> 16 half2 words
#define KP 16
#define AS_STRIDE 20           // u32 stride [m][kp]
#define WS_STRIDE 136          // u32 stride [kp][n]
#define A_TILE (BM * AS_STRIDE)
#define W_TILE (KP * WS_STRIDE)
#define OFF_W  (2 * A_TILE)
#define OFF_BIAS (2 * A_TILE + 2 * W_TILE)
#define SMEM_BYTES ((2 * A_TILE + 2 * W_TILE + 128) * 4)   // 38400 B

#define MAXS 150016            // max padded row count for g_xt

// Pre-scaled fp16x2-packed weights, [job][kp][n=128] u32
__device__ uint32_t g_wt[147456];
// Transposed x: g_xt[c * S + r], c in [0,640)
__device__ float g_xt[640ull * MAXS];

__device__ __forceinline__ uint32_t smem_u32(const void* p) {
    uint32_t a;
    asm("{ .reg .u64 t; cvta.to.shared.u64 t, %1; cvt.u32.u64 %0, t; }" : "=r"(a) : "l"(p));
    return a;
}
__device__ __forceinline__ void cp16(uint32_t dst, const void* src) {
    asm volatile("cp.async.ca.shared.global [%0], [%1], 16;" :: "r"(dst), "l"(src));
}
__device__ __forceinline__ uint32_t pack_h2(float lo, float hi) {
    half2 h = __floats2half2_rn(lo, hi);
    return *(uint32_t*)&h;
}
__device__ __forceinline__ void mma_f16(float* d, const uint32_t* a, const uint32_t* b) {
    asm volatile(
        "mma.sync.aligned.m16n8k16.row.col.f32.f16.f16.f32 "
        "{%0,%1,%2,%3}, {%4,%5,%6,%7}, {%8,%9}, {%0,%1,%2,%3};"
        : "+f"(d[0]), "+f"(d[1]), "+f"(d[2]), "+f"(d[3])
        : "r"(a[0]), "r"(a[1]), "r"(a[2]), "r"(a[3]), "r"(b[0]), "r"(b[1]));
}

// ---------------- prep: transpose x -> g_xt ----------------
__global__ void prep_xt(const float* __restrict__ x, int B, int S)
{
    __shared__ float t[32][33];
    const int tx = threadIdx.x, ty = threadIdx.y;
    const int c0 = blockIdx.x * 32;
    const int r0 = blockIdx.y * 32;
    #pragma unroll
    for (int i = 0; i < 4; i++) {
        int r = r0 + ty + i * 8;
        t[ty + i * 8][tx] = (r < B) ? x[(size_t)r * 640 + c0 + tx] : 0.0f;
    }
    __syncthreads();
    #pragma unroll
    for (int i = 0; i < 4; i++) {
        int c = c0 + ty + i * 8;
        g_xt[(size_t)c * S + r0 + tx] = t[tx][ty + i * 8];
    }
}

// ---------------- prep: fold scales + fp16 pack (k-pairs) ----------------
__global__ void prep_wt(const float* __restrict__ w000, const float* __restrict__ w110,
                        const float* __restrict__ w011, const float* __restrict__ w101,
                        const float* __restrict__ w111)
{
    const float SQK0 = 0.05103103630798288f;
    const float SQK1 = 0.04419417382415922f;
    const float IS3  = 0.57735026918962584f;
    const float IS2  = 0.70710678118654752f;

    int idx = blockIdx.x * 256 + threadIdx.x;
    if (idx >= 147456) return;
    int job, rem;
    if (idx < 49152) { job = idx / 24576; rem = idx % 24576; }
    else             { int t = idx - 49152; job = 2 + t / 32768; rem = t % 32768; }
    int kp = rem >> 7, n = rem & 127;

    float w2[2];
    #pragma unroll
    for (int h = 0; h < 2; h++) {
        int k = 2 * kp + h;
        float v;
        if (job < 2) {
            int cb = job;
            if (k < 256) v = SQK0 * w000[k * 256 + cb * 128 + n];
            else         v = SQK0 * IS3 * w110[(k - 256) * 256 + cb * 128 + n];
        } else {
            if (k < 256)      v = SQK1 * w011[k * 128 + n];
            else if (k < 384) v = SQK1 * w101[(k - 256) * 128 + n];
            else              v = SQK1 * IS2 * w111[(k - 384) * 128 + n];
        }
        w2[h] = v;
    }
    g_wt[idx] = pack_h2(w2[0], w2[1]);
}

// ---------------- main kernel ----------------
__global__ void __launch_bounds__(NT, 2)
tpr_kernel(const float* __restrict__ y, const float* __restrict__ b0,
           float* __restrict__ out, int B, int S)
{
    extern __shared__ uint32_t sm[];
    const uint32_t sb = smem_u32(sm);

    const int job  = blockIdx.x;
    const int row0 = blockIdx.y * BM;
    const int tid  = threadIdx.x;
    const int wid  = tid >> 5;
    const int lane = tid & 31;
    const int qr   = lane >> 2;
    const int qc   = lane & 3;
    const int wm   = wid & 3;     // warp m (32 rows)
    const int wn   = wid >> 2;    // warp n (64 cols)

    int region, cb;
    if (job < 2) { region = 0; cb = job; } else { region = job - 1; cb = 0; }
    const int i0 = region - 1;
    const int j1 = (i0 + 1) % 3;
    const int j2 = (i0 + 2) % 3;
    const int KT = (region == 0) ? 12 : 16;
    const uint32_t* wbase = g_wt + ((job < 2) ? job * 24576 : 49152 + (job - 2) * 32768);

    // staging role: one row per thread-pair, 16 k per thread
    const int fm   = tid >> 1;
    const int klo  = (tid & 1) * 16;       // k offset within BK
    const int kwo  = (tid & 1) * 8;        // word offset within KP
    const int frow = row0 + fm;
    const bool valid = frow < B;
    float yv[4] = {0.f, 0.f, 0.f, 0.f};
    if (valid) {
        float4 t = *(const float4*)(y + (size_t)frow * 4);
        yv[0] = t.x; yv[1] = t.y; yv[2] = t.z; yv[3] = t.w;
    }
    if (region == 0 && tid < 128)
        ((float*)(sm + OFF_BIAS))[tid] = b0[cb * 128 + tid];

    float acc[2][8][4];
    #pragma unroll
    for (int mi = 0; mi < 2; mi++)
        #pragma unroll
        for (int ni = 0; ni < 8; ni++)
            #pragma unroll
            for (int c = 0; c < 4; c++) acc[mi][ni][c] = 0.f;

    // ---- W tile: cp.async straight copy (pre-packed fp16x2) ----
    auto issueW = [&](int kt, int b) {
        const uint32_t dbase = sb + (OFF_W + b * W_TILE) * 4;
        const uint32_t* src = wbase + (size_t)(kt * KP) * 128;
        #pragma unroll
        for (int i = 0; i < 2; i++) {
            int idx = tid + i * NT;
            int kw = idx >> 5, c16 = idx & 31;
            cp16(dbase + (uint32_t)(kw * WS_STRIDE + c16 * 4) * 4,
                 src + kw * 128 + c16 * 4);
        }
        asm volatile("cp.async.commit_group;" ::: "memory");
    };

    // ---- A tile: gated features from transposed x (coalesced columns) ----
    auto load_feat = [&](int kt, float* f) {
        const int kg0 = kt * BK + klo;
        if (!valid) {
            #pragma unroll
            for (int j = 0; j < 16; j++) f[j] = 0.f;
        } else if (kg0 < 256) {
            float s = (region == 0) ? yv[0] : yv[1 + i0];
            const float* cp = g_xt + (size_t)kg0 * S + frow;
            #pragma unroll
            for (int j = 0; j < 16; j++)
                f[j] = cp[(size_t)j * S] * s;
        } else {
            int u0, mode;
            if (region == 0)    { u0 = kg0 - 256; mode = 0; }
            else if (kg0 < 384) { u0 = kg0 - 256; mode = 1; }
            else                { u0 = kg0 - 384; mode = 2; }
            const float* bp = g_xt + (size_t)(256 + 3 * u0) * S + frow;
            if (mode == 0) {
                #pragma unroll
                for (int j = 0; j < 16; j++) {
                    float e0 = bp[(size_t)(3*j)   * S];
                    float e1 = bp[(size_t)(3*j+1) * S];
                    float e2 = bp[(size_t)(3*j+2) * S];
                    f[j] = e0 * yv[1] + e1 * yv[2] + e2 * yv[3];
                }
            } else if (mode == 1) {
                #pragma unroll
                for (int j = 0; j < 16; j++)
                    f[j] = bp[(size_t)(3*j + i0) * S] * yv[0];
            } else {
                #pragma unroll
                for (int j = 0; j < 16; j++) {
                    float xa = bp[(size_t)(3*j + j1) * S];
                    float xb = bp[(size_t)(3*j + j2) * S];
                    f[j] = xa * yv[1 + j2] - xb * yv[1 + j1];
                }
            }
        }
    };
    auto storeA = [&](int b, const float* f) {
        uint32_t* ap = sm + b * A_TILE + fm * AS_STRIDE + kwo;
        uint4 u0 = make_uint4(pack_h2(f[0], f[1]),   pack_h2(f[2], f[3]),
                              pack_h2(f[4], f[5]),   pack_h2(f[6], f[7]));
        uint4 u1 = make_uint4(pack_h2(f[8], f[9]),   pack_h2(f[10], f[11]),
                              pack_h2(f[12], f[13]), pack_h2(f[14], f[15]));
        *(uint4*)(ap)     = u0;
        *(uint4*)(ap + 4) = u1;
    };

    // ---------- prologue ----------
    float f[16];
    issueW(0, 0);
    load_feat(0, f);
    storeA(0, f);

    // ---------- main loop: 1 barrier / tile, cp.async overlapped ----------
    for (int kt = 0; kt < KT; kt++) {
        const int b = kt & 1;
        asm volatile("cp.async.wait_group 0;" ::: "memory");
        __syncthreads();

        const bool more = (kt + 1 < KT);
        if (more) { issueW(kt + 1, b ^ 1); load_feat(kt + 1, f); }

        const uint32_t* Ab = sm + b * A_TILE;
        const uint32_t* Wb = sm + OFF_W + b * W_TILE;
        #pragma unroll
        for (int ks = 0; ks < 2; ks++) {
            const int base = ks * 8;
            uint32_t a[2][4];
            #pragma unroll
            for (int mi = 0; mi < 2; mi++) {
                const uint32_t* p = &Ab[(wm * 32 + mi * 16 + qr) * AS_STRIDE + base + qc];
                a[mi][0] = p[0];
                a[mi][1] = p[8 * AS_STRIDE];
                a[mi][2] = p[4];
                a[mi][3] = p[8 * AS_STRIDE + 4];
            }
            #pragma unroll
            for (int ni = 0; ni < 8; ni++) {
                uint32_t bb[2];
                const uint32_t* q = &Wb[(base + qc) * WS_STRIDE + wn * 64 + ni * 8 + qr];
                bb[0] = q[0];
                bb[1] = q[4 * WS_STRIDE];
                mma_f16(acc[0][ni], a[0], bb);
                mma_f16(acc[1][ni], a[1], bb);
            }
        }

        if (more) storeA(b ^ 1, f);
    }

    // ---------- epilogue ----------
    const float* bias = (const float*)(sm + OFF_BIAS);
    #pragma unroll
    for (int mi = 0; mi < 2; mi++) {
        #pragma unroll
        for (int half = 0; half < 2; half++) {
            int row = row0 + wm * 32 + mi * 16 + qr + half * 8;
            if (row >= B) continue;
            if (region == 0) {
                float* o = out + (size_t)row * 640 + cb * 128;
                #pragma unroll
                for (int ni = 0; ni < 8; ni++) {
                    int col = wn * 64 + ni * 8 + qc * 2;
                    float2 v = make_float2(acc[mi][ni][half * 2]     + bias[col],
                                           acc[mi][ni][half * 2 + 1] + bias[col + 1]);
                    *(float2*)(o + col) = v;
                }
            } else {
                float* o = out + (size_t)row * 640 + 256 + i0;
                #pragma unroll
                for (int ni = 0; ni < 8; ni++) {
                    int col = wn * 64 + ni * 8 + qc * 2;
                    o[col * 3]       = acc[mi][ni][half * 2];
                    o[(col + 1) * 3] = acc[mi][ni][half * 2 + 1];
                }
            }
        }
    }
}

extern "C" void kernel_launch(void* const* d_in, const int* in_sizes, int n_in,
                              void* d_out, int out_size)
{
    const float* x    = (const float*)d_in[0];
    const float* y    = (const float*)d_in[1];
    const float* w000 = (const float*)d_in[2];
    const float* w110 = (const float*)d_in[3];
    const float* w011 = (const float*)d_in[4];
    const float* w101 = (const float*)d_in[5];
    const float* w111 = (const float*)d_in[6];
    const float* b0   = (const float*)d_in[7];
    int B = in_sizes[0] / 640;
    int S = (B + 127) & ~127;
    if (S > MAXS) S = MAXS;

    cudaFuncSetAttribute(tpr_kernel, cudaFuncAttributeMaxDynamicSharedMemorySize,
                         SMEM_BYTES);

    prep_wt<<<(147456 + 255) / 256, 256>>>(w000, w110, w011, w101, w111);
    {
        dim3 tb(32, 8), tg(640 / 32, S / 32);
        prep_xt<<<tg, tb>>>(x, B, S);
    }

    dim3 grid(5, (B + BM - 1) / BM);
    tpr_kernel<<<grid, NT, SMEM_BYTES>>>(y, b0, (float*)d_out, B, S);
}